// round 9
// baseline (speedup 1.0000x reference)
#include <cuda_runtime.h>
#include <cuda_bf16.h>
#include <cstdint>

// Problem constants
#define BATCH  256
#define DI     5120
#define RNK    160
#define NS     16
#define NC     192          // 160 (W_delta) + 16 (W_B) + 16 (W_C)
#define KSPLIT 40
#define KCHUNK 128          // DI / KSPLIT

// Scratch (device globals — no allocations allowed)
__device__ float g_Ppart[KSPLIT * BATCH * NC];
__device__ float g_P[BATCH * NC];                // [xd | Bp | C]
__device__ float g_negA[DI * NS];
__device__ float g_dt[BATCH * DI];

// ---- standard sm_80+ bf16 tensor-core mma (legal on compute_103) ----
__device__ __forceinline__ void mma16816(float* c, const uint32_t* a, const uint32_t* b) {
    asm volatile(
        "mma.sync.aligned.m16n8k16.row.col.f32.bf16.bf16.f32 "
        "{%0,%1,%2,%3}, {%4,%5,%6,%7}, {%8,%9}, {%0,%1,%2,%3};"
        : "+f"(c[0]), "+f"(c[1]), "+f"(c[2]), "+f"(c[3])
        : "r"(a[0]), "r"(a[1]), "r"(a[2]), "r"(a[3]), "r"(b[0]), "r"(b[1]));
}

// hi/lo bf16 split: v = hi + lo to ~16-bit mantissa accuracy
__device__ __forceinline__ void split1(float v, unsigned short& h, unsigned short& l) {
    __nv_bfloat16 bh = __float2bfloat16(v);
    __nv_bfloat16 bl = __float2bfloat16(v - __bfloat162float(bh));
    h = __bfloat16_as_ushort(bh);
    l = __bfloat16_as_ushort(bl);
}

// fast exp on FMA/ALU pipes, |rel err| ~1e-7
__device__ __forceinline__ float fast_expf(float x) {
    x = fmaxf(x, -87.0f);
    float r  = fmaf(x, 1.442695041f, 12582912.0f);
    float fi = r - 12582912.0f;
    int   ib = __float_as_int(r) - 0x4B400000;
    float f  = fmaf(x, 1.442695041f, -fi);
    float p  = 1.5403530e-4f;
    p = fmaf(p, f, 1.3333558e-3f);
    p = fmaf(p, f, 9.6181292e-3f);
    p = fmaf(p, f, 5.5504109e-2f);
    p = fmaf(p, f, 2.4022651e-1f);
    p = fmaf(p, f, 6.9314718e-1f);
    p = fmaf(p, f, 1.0f);
    return __int_as_float(__float_as_int(p) + (ib << 23));
}

// ---------------------------------------------------------------------------
// K1: tensor-core split-K GEMM1.
// Tile: 64 m x 192 n x 128 k per CTA. grid (4 m, 40 z) = 160 CTAs, 256 thr.
// A/B staged in smem as bf16 hi/lo ([m][k] / [n][k], padded rows -> fragment
// LDS conflict-free). 3 mma passes (hh, hl, lh) into fp32 regs.
// A-pad 136: stride 68 words; lanes hit words {4g+t} -> all 32 banks.
// ---------------------------------------------------------------------------
#define K1_APAD 136
#define K1_BPAD 136
#define K1_AH 0
#define K1_AL (64 * K1_APAD)
#define K1_BH (2 * 64 * K1_APAD)
#define K1_BL (2 * 64 * K1_APAD + 192 * K1_BPAD)
#define K1_SMEM ((2 * 64 * K1_APAD + 2 * 192 * K1_BPAD) * 2)   // 139264 B

__global__ __launch_bounds__(256)
void k1_mma(const float* __restrict__ X,
            const float* __restrict__ Wd,
            const float* __restrict__ WB,
            const float* __restrict__ WC)
{
    extern __shared__ unsigned short sm[];
    const int tid  = threadIdx.x;
    const int wid  = tid >> 5;
    const int lane = tid & 31;
    const int g    = lane >> 2;      // group row
    const int t    = lane & 3;       // thread-in-group
    const int wm   = wid >> 2;       // warp m half (0..1)
    const int wn   = wid & 3;        // warp n quarter (0..3)
    const int m0   = blockIdx.x * 64;
    const int k0   = blockIdx.y * KCHUNK;

    // ---- stage A (64 m x 128 k) hi/lo ----
    for (int idx = tid; idx < 64 * 128; idx += 256) {
        int m = idx >> 7, k = idx & 127;
        unsigned short h, l;
        split1(X[(size_t)(m0 + m) * DI + k0 + k], h, l);
        sm[K1_AH + m * K1_APAD + k] = h;
        sm[K1_AL + m * K1_APAD + k] = l;
    }
    // ---- stage B (128 k x 192 n) transposed to [n][k], hi/lo ----
    for (int idx = tid; idx < 128 * 192; idx += 256) {
        int k = idx / 192, j = idx - k * 192;
        int kg = k0 + k;
        float w;
        if (j < 160)      w = Wd[(size_t)kg * 160 + j];
        else if (j < 176) w = WB[(size_t)kg * 16 + (j - 160)];
        else              w = WC[(size_t)kg * 16 + (j - 176)];
        unsigned short h, l;
        split1(w, h, l);
        sm[K1_BH + j * K1_BPAD + k] = h;
        sm[K1_BL + j * K1_BPAD + k] = l;
    }
    __syncthreads();

    float acc[2][6][4] = {};
    #pragma unroll
    for (int ks = 0; ks < 8; ks++) {
        const int kb = ks * 16;
        uint32_t ah[2][4], al[2][4];
        #pragma unroll
        for (int mi = 0; mi < 2; mi++) {
            const int r0 = (wm * 32 + mi * 16 + g) * K1_APAD + kb + 2 * t;
            const int r1 = r0 + 8 * K1_APAD;
            ah[mi][0] = *(const uint32_t*)&sm[K1_AH + r0];
            ah[mi][1] = *(const uint32_t*)&sm[K1_AH + r1];
            ah[mi][2] = *(const uint32_t*)&sm[K1_AH + r0 + 8];
            ah[mi][3] = *(const uint32_t*)&sm[K1_AH + r1 + 8];
            al[mi][0] = *(const uint32_t*)&sm[K1_AL + r0];
            al[mi][1] = *(const uint32_t*)&sm[K1_AL + r1];
            al[mi][2] = *(const uint32_t*)&sm[K1_AL + r0 + 8];
            al[mi][3] = *(const uint32_t*)&sm[K1_AL + r1 + 8];
        }
        uint32_t bh[6][2], bl[6][2];
        #pragma unroll
        for (int ni = 0; ni < 6; ni++) {
            const int c0 = (wn * 48 + ni * 8 + g) * K1_BPAD + kb + 2 * t;
            bh[ni][0] = *(const uint32_t*)&sm[K1_BH + c0];
            bh[ni][1] = *(const uint32_t*)&sm[K1_BH + c0 + 8];
            bl[ni][0] = *(const uint32_t*)&sm[K1_BL + c0];
            bl[ni][1] = *(const uint32_t*)&sm[K1_BL + c0 + 8];
        }
        #pragma unroll
        for (int mi = 0; mi < 2; mi++)
            #pragma unroll
            for (int ni = 0; ni < 6; ni++) {
                mma16816(acc[mi][ni], ah[mi], bh[ni]);   // hi*hi
                mma16816(acc[mi][ni], ah[mi], bl[ni]);   // hi*lo
                mma16816(acc[mi][ni], al[mi], bh[ni]);   // lo*hi
            }
    }
    __syncthreads();   // all fragment reads done; smem can be reused

    // ---- epilogue: regs -> padded smem stage -> coalesced partial write ----
    float* stage = (float*)sm;       // 64 x 196
    #pragma unroll
    for (int mi = 0; mi < 2; mi++)
        #pragma unroll
        for (int ni = 0; ni < 6; ni++) {
            const int row = wm * 32 + mi * 16 + g;
            const int col = wn * 48 + ni * 8 + 2 * t;
            stage[row * 196 + col]           = acc[mi][ni][0];
            stage[row * 196 + col + 1]       = acc[mi][ni][1];
            stage[(row + 8) * 196 + col]     = acc[mi][ni][2];
            stage[(row + 8) * 196 + col + 1] = acc[mi][ni][3];
        }
    __syncthreads();
    float* out = g_Ppart + (size_t)blockIdx.y * (BATCH * NC) + (size_t)m0 * NC;
    for (int idx = tid; idx < 64 * 192; idx += 256) {
        int m = idx / 192, n = idx - m * 192;
        out[idx] = stage[m * 196 + n];
    }
}

// ---------------------------------------------------------------------------
// K1b: reduce split-K partials -> g_P; precompute g_negA = -exp(A_log).
// ---------------------------------------------------------------------------
__global__ __launch_bounds__(256)
void k1b_reduce(const float* __restrict__ A_log)
{
    int i = blockIdx.x * 256 + threadIdx.x;
    if (i < BATCH * NC) {
        float s = 0.f;
        #pragma unroll
        for (int p = 0; p < KSPLIT; p++)
            s += g_Ppart[(size_t)p * (BATCH * NC) + i];
        g_P[i] = s;
    }
    if (i < DI * NS)
        g_negA[i] = -__expf(A_log[i]);
}

// ---------------------------------------------------------------------------
// K2: tensor-core GEMM2. dt = softplus(xd(256x160) @ W_dt(160x5120) + b_dt).
// Tile: 64 m x 128 n x 160 k per CTA. grid (40 n, 4 m) = 160 CTAs, 256 thr.
// A-pad 168: stride 84 words mod 32 = 20 -> lanes hit distinct banks.
// ---------------------------------------------------------------------------
#define K2_APAD 168
#define K2_BPAD 168
#define K2_AH 0
#define K2_AL (64 * K2_APAD)
#define K2_BH (2 * 64 * K2_APAD)
#define K2_BL (2 * 64 * K2_APAD + 128 * K2_BPAD)
#define K2_SMEM ((2 * 64 * K2_APAD + 2 * 128 * K2_BPAD) * 2)   // 129024 B

__global__ __launch_bounds__(256)
void k2_mma(const float* __restrict__ Wdt,
            const float* __restrict__ bdt)
{
    extern __shared__ unsigned short sm[];
    const int tid  = threadIdx.x;
    const int wid  = tid >> 5;
    const int lane = tid & 31;
    const int g    = lane >> 2;
    const int t    = lane & 3;
    const int wm   = wid >> 2;       // 0..1
    const int wn   = wid & 3;        // 0..3
    const int n0   = blockIdx.x * 128;
    const int m0   = blockIdx.y * 64;

    // ---- stage A = xd (64 m x 160 k) from g_P, hi/lo ----
    for (int idx = tid; idx < 64 * 160; idx += 256) {
        int m = idx / 160, k = idx - m * 160;
        unsigned short h, l;
        split1(g_P[(size_t)(m0 + m) * NC + k], h, l);
        sm[K2_AH + m * K2_APAD + k] = h;
        sm[K2_AL + m * K2_APAD + k] = l;
    }
    // ---- stage B = W_dt (160 k x 128 n) transposed to [n][k], hi/lo ----
    for (int idx = tid; idx < 160 * 128; idx += 256) {
        int k = idx >> 7, n = idx & 127;
        unsigned short h, l;
        split1(Wdt[(size_t)k * DI + n0 + n], h, l);
        sm[K2_BH + n * K2_BPAD + k] = h;
        sm[K2_BL + n * K2_BPAD + k] = l;
    }
    __syncthreads();

    float acc[2][4][4] = {};
    #pragma unroll
    for (int ks = 0; ks < 10; ks++) {
        const int kb = ks * 16;
        uint32_t ah[2][4], al[2][4];
        #pragma unroll
        for (int mi = 0; mi < 2; mi++) {
            const int r0 = (wm * 32 + mi * 16 + g) * K2_APAD + kb + 2 * t;
            const int r1 = r0 + 8 * K2_APAD;
            ah[mi][0] = *(const uint32_t*)&sm[K2_AH + r0];
            ah[mi][1] = *(const uint32_t*)&sm[K2_AH + r1];
            ah[mi][2] = *(const uint32_t*)&sm[K2_AH + r0 + 8];
            ah[mi][3] = *(const uint32_t*)&sm[K2_AH + r1 + 8];
            al[mi][0] = *(const uint32_t*)&sm[K2_AL + r0];
            al[mi][1] = *(const uint32_t*)&sm[K2_AL + r1];
            al[mi][2] = *(const uint32_t*)&sm[K2_AL + r0 + 8];
            al[mi][3] = *(const uint32_t*)&sm[K2_AL + r1 + 8];
        }
        uint32_t bh[4][2], bl[4][2];
        #pragma unroll
        for (int ni = 0; ni < 4; ni++) {
            const int c0 = (wn * 32 + ni * 8 + g) * K2_BPAD + kb + 2 * t;
            bh[ni][0] = *(const uint32_t*)&sm[K2_BH + c0];
            bh[ni][1] = *(const uint32_t*)&sm[K2_BH + c0 + 8];
            bl[ni][0] = *(const uint32_t*)&sm[K2_BL + c0];
            bl[ni][1] = *(const uint32_t*)&sm[K2_BL + c0 + 8];
        }
        #pragma unroll
        for (int mi = 0; mi < 2; mi++)
            #pragma unroll
            for (int ni = 0; ni < 4; ni++) {
                mma16816(acc[mi][ni], ah[mi], bh[ni]);
                mma16816(acc[mi][ni], ah[mi], bl[ni]);
                mma16816(acc[mi][ni], al[mi], bh[ni]);
            }
    }
    __syncthreads();

    // ---- epilogue: regs -> smem stage -> softplus -> coalesced g_dt ----
    float* stage = (float*)sm;       // 64 x 132
    #pragma unroll
    for (int mi = 0; mi < 2; mi++)
        #pragma unroll
        for (int ni = 0; ni < 4; ni++) {
            const int row = wm * 32 + mi * 16 + g;
            const int col = wn * 32 + ni * 8 + 2 * t;
            stage[row * 132 + col]           = acc[mi][ni][0];
            stage[row * 132 + col + 1]       = acc[mi][ni][1];
            stage[(row + 8) * 132 + col]     = acc[mi][ni][2];
            stage[(row + 8) * 132 + col + 1] = acc[mi][ni][3];
        }
    __syncthreads();
    for (int idx = tid; idx < 64 * 128; idx += 256) {
        int m = idx >> 7, n = idx & 127;
        float z = stage[m * 132 + n] + bdt[n0 + n];
        float sp = (z > 20.f) ? z : log1pf(__expf(z));
        g_dt[(size_t)(m0 + m) * DI + n0 + n] = sp;
    }
}

// ---------------------------------------------------------------------------
// K3: fused readout, warp-cooperative + explicit prefetch (high MLP).
// 4 lanes per (b,d) row; ALL 4 row-groups' loads issued before any compute.
// ---------------------------------------------------------------------------
__global__ __launch_bounds__(256)
void k3_main(const float* __restrict__ x,
             const float* __restrict__ h,
             const float* __restrict__ Dv,
             float* __restrict__ y)
{
    const int tid  = threadIdx.x;
    const int warp = tid >> 5;
    const int lane = tid & 31;
    const int r = lane >> 2;
    const int c = lane & 3;
    const int base = blockIdx.x * 256;
    const int b = base / DI;                 // constant per block (DI % 256 == 0)

    __shared__ __align__(16) float sC[16];
    __shared__ __align__(16) float sB[16];
    if (tid < 16)       sC[tid]      = g_P[(size_t)b * NC + 176 + tid];
    else if (tid < 32)  sB[tid - 16] = g_P[(size_t)b * NC + 160 + (tid - 16)];
    __syncthreads();

    const float4 cv = *(const float4*)&sC[c * 4];
    const float4 bv = *(const float4*)&sB[c * 4];
    float bc = fmaf(bv.x, cv.x, fmaf(bv.y, cv.y, fmaf(bv.z, cv.z, bv.w * cv.w)));
    bc += __shfl_xor_sync(0xffffffffu, bc, 1);
    bc += __shfl_xor_sync(0xffffffffu, bc, 2);

    const int row0 = base + warp * 32 + r;
    float4 hv[4], av[4];
    float dtv[4], xv[4];
    #pragma unroll
    for (int s = 0; s < 4; s++) {            // all loads issued up-front
        const int row = row0 + s * 8;
        hv[s]  = *(const float4*)(h      + (size_t)row * NS + c * 4);
        av[s]  = *(const float4*)(g_negA + (size_t)(row - b * DI) * NS + c * 4);
        dtv[s] = g_dt[row];
        xv[s]  = x[row];
    }
    #pragma unroll
    for (int s = 0; s < 4; s++) {
        const int row = row0 + s * 8;
        const float dt = dtv[s];
        float p;
        p = fast_expf(dt * av[s].x) * hv[s].x * cv.x;
        p = fmaf(fast_expf(dt * av[s].y) * hv[s].y, cv.y, p);
        p = fmaf(fast_expf(dt * av[s].z) * hv[s].z, cv.z, p);
        p = fmaf(fast_expf(dt * av[s].w) * hv[s].w, cv.w, p);
        p += __shfl_xor_sync(0xffffffffu, p, 1);
        p += __shfl_xor_sync(0xffffffffu, p, 2);
        if (c == 0)
            y[row] = p + dt * xv[s] * bc + xv[s] * Dv[row - b * DI];
    }
}

// ---------------------------------------------------------------------------
// Launch. Input order: x, h, W_delta, W_dt, b_dt, A_log, W_B, W_C, D
// ---------------------------------------------------------------------------
extern "C" void kernel_launch(void* const* d_in, const int* in_sizes, int n_in,
                              void* d_out, int out_size)
{
    const float* x      = (const float*)d_in[0];
    const float* h      = (const float*)d_in[1];
    const float* Wdelta = (const float*)d_in[2];
    const float* Wdt    = (const float*)d_in[3];
    const float* bdt    = (const float*)d_in[4];
    const float* Alog   = (const float*)d_in[5];
    const float* WB     = (const float*)d_in[6];
    const float* WC     = (const float*)d_in[7];
    const float* Dv     = (const float*)d_in[8];
    float* y = (float*)d_out;

    cudaFuncSetAttribute(k1_mma, cudaFuncAttributeMaxDynamicSharedMemorySize, K1_SMEM);
    cudaFuncSetAttribute(k2_mma, cudaFuncAttributeMaxDynamicSharedMemorySize, K2_SMEM);

    dim3 g1(BATCH / 64, KSPLIT);                       // 4 x 40 = 160 CTAs
    k1_mma<<<g1, 256, K1_SMEM>>>(x, Wdelta, WB, WC);

    k1b_reduce<<<(DI * NS + 255) / 256, 256>>>(Alog);  // 320 blocks

    dim3 g2(DI / 128, BATCH / 64);                     // 40 x 4 = 160 CTAs
    k2_mma<<<g2, 256, K2_SMEM>>>(Wdt, bdt);

    k3_main<<<(BATCH * DI) / 256, 256>>>(x, h, Dv, y);
}